// round 12
// baseline (speedup 1.0000x reference)
#include <cuda_runtime.h>
#include <cuda_fp16.h>
#include <cstdint>
#include <math.h>

#define BV      4
#define NTOK    16384
#define DIMM    512
#define HEADS   8
#define DH      64
#define SEGLEN  64
#define PMT     4

// ---------------- scratch (device globals; no allocation) ----------------
__device__ float  g_rms[BV * NTOK];
__device__ float  g_rope[NTOK * 64];
__device__ __half g_xt[(size_t)BV * NTOK * DIMM];      // fp16 x, K-permuted per 32-block
__device__ __half g_wqkvT[1536 * DIMM];                // fp16(gamma*[Wq|Wkv])^T, K-permuted
__device__ __half g_woT[DIMM * DIMM];                  // fp16(Wo)^T, K-permuted
__device__ float  g_q[(size_t)BV * HEADS * NTOK * DH];
__device__ float  g_k[(size_t)BV * HEADS * NTOK * DH];
__device__ float  g_vfb[(size_t)BV * HEADS * NTOK * DH];
__device__ __half g_att[(size_t)BV * NTOK * DIMM];     // fp16 attention out, K-permuted

// K-permutation within each 32-block (fragment halves contiguous per thread)
__device__ __forceinline__ int kperm(int k) {
    return (((k >> 1) & 3) << 3) + (((k >> 3) & 3) << 1) + (k & 1);
}

// ---------------- cp.async helpers ----------------
__device__ __forceinline__ void cp16a(uint32_t smem, const void* g) {
    asm volatile("cp.async.cg.shared.global [%0], [%1], 16;\n" ::"r"(smem), "l"(g));
}
__device__ __forceinline__ void cp_commit() { asm volatile("cp.async.commit_group;\n"); }
__device__ __forceinline__ void cp_wait1() { asm volatile("cp.async.wait_group 1;\n"); }
__device__ __forceinline__ void cp_wait0() { asm volatile("cp.async.wait_group 0;\n"); }

// ---------------- rope table ----------------
__global__ void rope_table_kernel() {
    int idx = blockIdx.x * blockDim.x + threadIdx.x;
    if (idx >= NTOK * 32) return;
    int n = idx >> 5, i = idx & 31;
    double p = pow(10000.0, (double)i / 32.0);
    float inv = 1.0f / (float)p;
    float th = (float)n * inv;
    float s, c;
    sincosf(th, &s, &c);
    g_rope[idx * 2 + 0] = c;
    g_rope[idx * 2 + 1] = s;
}

// ---------------- prep_all: rms (+fp16 permuted x) AND wqkvT prep, one kernel ----------------
// blocks [0, 65536): rms rows; blocks [65536, 65536+6144): wqkvT elements
__global__ __launch_bounds__(128) void prep_all_kernel(const float* __restrict__ seq,
                                                       const float* __restrict__ normw,
                                                       const float* __restrict__ Wq,
                                                       const float* __restrict__ Wkv) {
    int bid = blockIdx.x;
    int t = threadIdx.x;
    if (bid < BV * NTOK) {
        int row = bid;
        const float4* p = (const float4*)(seq + (size_t)row * DIMM);
        float4 v = p[t];
        float ss = v.x * v.x + v.y * v.y + v.z * v.z + v.w * v.w;
#pragma unroll
        for (int o = 16; o; o >>= 1) ss += __shfl_xor_sync(0xffffffffu, ss, o);
        __shared__ float wsum[4];
        if ((t & 31) == 0) wsum[t >> 5] = ss;
        __syncthreads();
        if (t == 0) {
            float tot = wsum[0] + wsum[1] + wsum[2] + wsum[3];
            g_rms[row] = rsqrtf(tot * (1.0f / DIMM) + 1.1920929e-7f);
        }
        float vv[4] = {v.x, v.y, v.z, v.w};
        __half* dst = g_xt + (size_t)row * DIMM;
#pragma unroll
        for (int j = 0; j < 4; j++) {
            int k = t * 4 + j;
            dst[(k & ~31) + kperm(k & 31)] = __float2half_rn(vv[j]);
        }
    } else {
        int idx = (bid - BV * NTOK) * 128 + t;
        if (idx < 1536 * DIMM) {
            int n = idx >> 9, kpf = idx & 511;
            int kp = kpf & 31;
            int k = (kpf & ~31) + 8 * ((kp & 7) >> 1) + 2 * (kp >> 3) + (kp & 1);
            float w = (n < 512) ? Wq[k * 512 + n] : Wkv[k * 1024 + (n - 512)];
            g_wqkvT[idx] = __float2half_rn(normw[k] * w);
        }
    }
}

__global__ void prep_woT_kernel(const float* __restrict__ Wo) {
    int idx = blockIdx.x * blockDim.x + threadIdx.x;
    if (idx >= DIMM * DIMM) return;
    int n = idx >> 9, kpf = idx & 511;
    int kp = kpf & 31;
    int k = (kpf & ~31) + 8 * ((kp & 7) >> 1) + 2 * (kp >> 3) + (kp & 1);
    g_woT[idx] = __float2half_rn(Wo[k * 512 + n]);
}

// ================= GEMM core: fp16 m16n8k16 mma, BK=64, 3-stage cp.async ring =================
// Tile: BM=128, BN=128, BK=64. 256 threads, 8 warps (2m x 4n), warp tile 64x32.
// smem rows: 64 halves (128 B), conflict-free for cp.async and 16B frag loads.
#define HSTR 64
#define T_STG (128 * HSTR)                 // halves per stage-tile (8192)
#define NSTAGE 3
#define GEMM_SMEM (NSTAGE * 2 * T_STG * 2) // 98304 B

__device__ __forceinline__ void gemm_loadT(uint32_t sbase, const __half* src, int kbase, int t) {
#pragma unroll
    for (int i = 0; i < 4; i++) {
        int c = t + i * 256;
        int row = c >> 3, seg = c & 7;
        cp16a(sbase + (uint32_t)(row * HSTR + seg * 8) * 2,
              src + (size_t)row * DIMM + kbase + seg * 8);
    }
}

// one 32-K half-chunk of mma (32 mma instructions)
__device__ __forceinline__ void gemm_compute(const __half* aB, const __half* bB,
                                             float acc[4][4][4]) {
    uint4 av[4][2], bv[4];
#pragma unroll
    for (int mt = 0; mt < 4; mt++) {
        av[mt][0] = *(const uint4*)(aB + mt * 16 * HSTR);
        av[mt][1] = *(const uint4*)(aB + (mt * 16 + 8) * HSTR);
    }
#pragma unroll
    for (int nt = 0; nt < 4; nt++)
        bv[nt] = *(const uint4*)(bB + nt * 8 * HSTR);
#pragma unroll
    for (int h = 0; h < 2; h++) {
#pragma unroll
        for (int mt = 0; mt < 4; mt++) {
            uint32_t a0 = h ? av[mt][0].z : av[mt][0].x;
            uint32_t a1 = h ? av[mt][1].z : av[mt][1].x;
            uint32_t a2 = h ? av[mt][0].w : av[mt][0].y;
            uint32_t a3 = h ? av[mt][1].w : av[mt][1].y;
#pragma unroll
            for (int nt = 0; nt < 4; nt++) {
                uint32_t b0 = h ? bv[nt].z : bv[nt].x;
                uint32_t b1 = h ? bv[nt].w : bv[nt].y;
                asm volatile(
                    "mma.sync.aligned.m16n8k16.row.col.f32.f16.f16.f32 "
                    "{%0,%1,%2,%3},{%4,%5,%6,%7},{%8,%9},{%0,%1,%2,%3};"
                    : "+f"(acc[mt][nt][0]), "+f"(acc[mt][nt][1]),
                      "+f"(acc[mt][nt][2]), "+f"(acc[mt][nt][3])
                    : "r"(a0), "r"(a1), "r"(a2), "r"(a3),
                      "r"(b0), "r"(b1));
            }
        }
    }
}

// 8 K-chunks of 64, 3-stage ring, 1 sync/iter
__device__ __forceinline__ void gemm_mainloop(__half* sA, __half* sB,
                                              const __half* Ap, const __half* Bp,
                                              float acc[4][4][4],
                                              int aOff, int bOff, int t) {
    uint32_t aS = (uint32_t)__cvta_generic_to_shared(sA);
    uint32_t bS = (uint32_t)__cvta_generic_to_shared(sB);

    gemm_loadT(aS, Ap, 0, t);
    gemm_loadT(bS, Bp, 0, t);
    cp_commit();
    gemm_loadT(aS + T_STG * 2, Ap, 64, t);
    gemm_loadT(bS + T_STG * 2, Bp, 64, t);
    cp_commit();

    int cur = 0, nxt = 2;
#pragma unroll 1
    for (int kt = 0; kt < 8; kt++) {
        if (kt == 7) cp_wait0(); else cp_wait1();
        __syncthreads();
        if (kt + 2 < 8) {
            gemm_loadT(aS + nxt * (T_STG * 2), Ap, (kt + 2) * 64, t);
            gemm_loadT(bS + nxt * (T_STG * 2), Bp, (kt + 2) * 64, t);
            cp_commit();
        }
        const __half* aC = sA + cur * T_STG + aOff;
        const __half* bC = sB + cur * T_STG + bOff;
        gemm_compute(aC, bC, acc);          // k-halves 0..31 of this 64-chunk
        gemm_compute(aC + 32, bC + 32, acc);// k-halves 32..63
        cur = (cur == 2) ? 0 : cur + 1;
        nxt = (nxt == 2) ? 0 : nxt + 1;
    }
}

// ---------------- K2: QKV GEMM + RoPE epilogue ----------------
__global__ __launch_bounds__(256, 2) void qkv_kernel(float* __restrict__ vout_opt) {
    extern __shared__ __half smg[];
    __half* sA = smg;
    __half* sB = smg + NSTAGE * T_STG;

    float* vout = vout_opt ? vout_opt : g_vfb;

    int cb = blockIdx.x, rb = blockIdx.y;
    int r0 = rb * 128, c0 = cb * 128;
    int b = r0 >> 14, n0 = r0 & 16383;
    int sec = c0 >> 9;
    int srcb = sec ? (b ^ 2) : b;
    const __half* Ap = g_xt + ((size_t)srcb * NTOK + n0) * DIMM;
    const float* rmsp = g_rms + srcb * NTOK + n0;
    const __half* Bp = g_wqkvT + (size_t)c0 * DIMM;

    int t = threadIdx.x;
    int warp = t >> 5, lane = t & 31;
    int wm = warp >> 2, wn = warp & 3;
    int g = lane >> 2, t4 = lane & 3;
    int aOff = (wm * 64 + g) * HSTR + t4 * 8;
    int bOff = (wn * 32 + g) * HSTR + t4 * 8;

    float acc[4][4][4];
#pragma unroll
    for (int i = 0; i < 4; i++)
#pragma unroll
        for (int j = 0; j < 4; j++)
#pragma unroll
            for (int k = 0; k < 4; k++) acc[i][j][k] = 0.f;

    gemm_mainloop(sA, sB, Ap, Bp, acc, aOff, bOff, t);

#pragma unroll
    for (int mt = 0; mt < 4; mt++)
#pragma unroll
        for (int half = 0; half < 2; half++) {
            int rl = wm * 64 + mt * 16 + g + half * 8;
            float rs = rmsp[rl];
            int n = n0 + rl;
#pragma unroll
            for (int nt = 0; nt < 4; nt++) {
                int c = c0 + wn * 32 + nt * 8 + t4 * 2;
                float e = acc[mt][nt][half * 2 + 0] * rs;
                float o = acc[mt][nt][half * 2 + 1] * rs;
                if (sec < 2) {
                    int cc = c - sec * 512;
                    int h = cc >> 6, d = cc & 63;
                    int fi = d >> 1;
                    float cs = g_rope[((size_t)n * 32 + fi) * 2 + 0];
                    float sn = g_rope[((size_t)n * 32 + fi) * 2 + 1];
                    float re = e * cs - o * sn;
                    float ro = o * cs + e * sn;
                    float* dst = (sec == 0 ? g_q : g_k) +
                                 (((size_t)(b * HEADS + h) * NTOK + n) * DH + d);
                    *(float2*)dst = make_float2(re, ro);
                } else {
                    int cc = c - 1024;
                    int h = cc >> 6, d = cc & 63;
                    *(float2*)(vout + (((size_t)(b * HEADS + h) * NTOK + n) * DH + d)) =
                        make_float2(e, o);
                }
            }
        }
}

// ---------------- K4: output GEMM -> d_out ----------------
__global__ __launch_bounds__(256, 2) void outproj_kernel(float* __restrict__ out) {
    extern __shared__ __half smg[];
    __half* sA = smg;
    __half* sB = smg + NSTAGE * T_STG;

    int cb = blockIdx.x, rb = blockIdx.y;
    int r0 = rb * 128, c0 = cb * 128;
    const __half* Ap = g_att + (size_t)r0 * DIMM;
    const __half* Bp = g_woT + (size_t)c0 * DIMM;

    int t = threadIdx.x;
    int warp = t >> 5, lane = t & 31;
    int wm = warp >> 2, wn = warp & 3;
    int g = lane >> 2, t4 = lane & 3;
    int aOff = (wm * 64 + g) * HSTR + t4 * 8;
    int bOff = (wn * 32 + g) * HSTR + t4 * 8;

    float acc[4][4][4];
#pragma unroll
    for (int i = 0; i < 4; i++)
#pragma unroll
        for (int j = 0; j < 4; j++)
#pragma unroll
            for (int k = 0; k < 4; k++) acc[i][j][k] = 0.f;

    gemm_mainloop(sA, sB, Ap, Bp, acc, aOff, bOff, t);

#pragma unroll
    for (int mt = 0; mt < 4; mt++)
#pragma unroll
        for (int half = 0; half < 2; half++) {
            int r = r0 + wm * 64 + mt * 16 + g + half * 8;
#pragma unroll
            for (int nt = 0; nt < 4; nt++) {
                int c = c0 + wn * 32 + nt * 8 + t4 * 2;
                *(float2*)(out + (size_t)r * DIMM + c) =
                    make_float2(acc[mt][nt][half * 2 + 0], acc[mt][nt][half * 2 + 1]);
            }
        }
}

// ---------------- K3: windowed attention (register-tiled FFMA) ----------------
#define KSTR 68
#define ATT_SMEM ((64 * KSTR + 80 * KSTR + 64 * KSTR) * 4)

__global__ __launch_bounds__(256) void attn_kernel(const float* __restrict__ tm,
                                                   const float* __restrict__ vsrc_opt) {
    extern __shared__ float sm[];
    float* qs = sm;                    // 64 x 68
    float* ks = qs + 64 * KSTR;        // 80 x 68 (rows 68..79 zero)
    float* Ss = ks + 80 * KSTR;        // 64 x 68

    const float* vsrc = vsrc_opt ? vsrc_opt : g_vfb;

    int wh = blockIdx.x;
    int h = wh & 7, win = wh >> 3;
    int b = win >> 8, wi = win & 255;
    int n0 = wi * SEGLEN;
    int t = threadIdx.x;
    size_t base = ((size_t)(b * HEADS + h) * NTOK + n0) * DH;

#pragma unroll
    for (int i = 0; i < 4; i++) {
        int c = t + i * 256;
        int row = c >> 4, seg = c & 15;
        float4 v4 = *(const float4*)(g_q + base + (size_t)row * DH + seg * 4);
        *(float4*)&qs[row * KSTR + seg * 4] = v4;
    }
#pragma unroll
    for (int i = 0; i < 5; i++) {
        int c = t + i * 256;
        int row = c >> 4, seg = c & 15;
        float4 v4;
        if (row < PMT)
            v4 = *(const float4*)(tm + h * (PMT * DH) + row * DH + seg * 4);
        else if (row < 68)
            v4 = *(const float4*)(g_k + base + (size_t)(row - PMT) * DH + seg * 4);
        else
            v4 = make_float4(0.f, 0.f, 0.f, 0.f);
        *(float4*)&ks[row * KSTR + seg * 4] = v4;
    }
    __syncthreads();

    int tq = t >> 4, tj = t & 15;
    int qi0 = tq * 4, j0 = tj * 5;
    {
        float accS[4][5];
#pragma unroll
        for (int i = 0; i < 4; i++)
#pragma unroll
            for (int j = 0; j < 5; j++) accS[i][j] = 0.f;
#pragma unroll 4
        for (int d4 = 0; d4 < 64; d4 += 4) {
            float4 qv[4], kv[5];
#pragma unroll
            for (int i = 0; i < 4; i++) qv[i] = *(const float4*)&qs[(qi0 + i) * KSTR + d4];
#pragma unroll
            for (int j = 0; j < 5; j++) kv[j] = *(const float4*)&ks[(j0 + j) * KSTR + d4];
#pragma unroll
            for (int i = 0; i < 4; i++)
#pragma unroll
                for (int j = 0; j < 5; j++) {
                    accS[i][j] += qv[i].x * kv[j].x + qv[i].y * kv[j].y +
                                  qv[i].z * kv[j].z + qv[i].w * kv[j].w;
                }
        }
#pragma unroll
        for (int i = 0; i < 4; i++)
#pragma unroll
            for (int j = 0; j < 5; j++)
                if (j0 + j < 68) Ss[(qi0 + i) * KSTR + j0 + j] = accS[i][j] * 0.125f;
    }
    __syncthreads();

    {
        int row = t >> 2, q4 = t & 3;
        float* Sr = Ss + row * KSTR + q4 * 17;
        float m = -1e30f;
#pragma unroll
        for (int jj = 0; jj < 17; jj++) m = fmaxf(m, Sr[jj]);
        m = fmaxf(m, __shfl_xor_sync(0xffffffffu, m, 1));
        m = fmaxf(m, __shfl_xor_sync(0xffffffffu, m, 2));
        float s = 0.f;
#pragma unroll
        for (int jj = 0; jj < 17; jj++) {
            float e = expf(Sr[jj] - m);
            Sr[jj] = e;
            s += e;
        }
        s += __shfl_xor_sync(0xffffffffu, s, 1);
        s += __shfl_xor_sync(0xffffffffu, s, 2);
        float inv = 1.0f / s;
#pragma unroll
        for (int jj = 0; jj < 17; jj++) Sr[jj] *= inv;
    }
    __syncthreads();

    int td = t & 15, d0 = td * 4;
    float acc[4][4];
#pragma unroll
    for (int i = 0; i < 4; i++)
#pragma unroll
        for (int k = 0; k < 4; k++) acc[i][k] = 0.f;

    const float* tmv = tm + HEADS * PMT * DH + h * (PMT * DH);
#pragma unroll
    for (int j = 0; j < PMT; j++) {
        float4 v4 = *(const float4*)(tmv + j * DH + d0);
        float p[4];
#pragma unroll
        for (int i = 0; i < 4; i++) p[i] = Ss[(qi0 + i) * KSTR + j];
#pragma unroll
        for (int i = 0; i < 4; i++) {
            acc[i][0] += p[i] * v4.x; acc[i][1] += p[i] * v4.y;
            acc[i][2] += p[i] * v4.z; acc[i][3] += p[i] * v4.w;
        }
    }
#pragma unroll 4
    for (int j = PMT; j < 68; j++) {
        float4 v4 = *(const float4*)(vsrc + base + (size_t)(j - PMT) * DH + d0);
        float p[4];
#pragma unroll
        for (int i = 0; i < 4; i++) p[i] = Ss[(qi0 + i) * KSTR + j];
#pragma unroll
        for (int i = 0; i < 4; i++) {
            acc[i][0] += p[i] * v4.x; acc[i][1] += p[i] * v4.y;
            acc[i][2] += p[i] * v4.z; acc[i][3] += p[i] * v4.w;
        }
    }

    // fp16 K-permuted store into g_att
#pragma unroll
    for (int i = 0; i < 4; i++) {
        __half* op = g_att + ((size_t)(b * NTOK + n0 + qi0 + i)) * DIMM + h * DH;
#pragma unroll
        for (int j = 0; j < 4; j++) {
            int d = d0 + j;
            op[(d & ~31) + kperm(d & 31)] = __float2half_rn(acc[i][j]);
        }
    }
}

// ---------------- launch ----------------
extern "C" void kernel_launch(void* const* d_in, const int* in_sizes, int n_in,
                              void* d_out, int out_size) {
    const float *seq = 0, *normw = 0, *Wq = 0, *Wkv = 0, *Wo = 0, *tm = 0;
    for (int i = 0; i < n_in; i++) {
        int s = in_sizes[i];
        const float* p = (const float*)d_in[i];
        if (s == 33554432) seq = p;
        else if (s == 512) normw = p;
        else if (s == 524288) Wkv = p;
        else if (s == 4096) tm = p;
        else if (s == 262144) { if (!Wq) Wq = p; else Wo = p; }
    }
    float* out = (float*)d_out;
    float* vout = (out_size >= 67108864) ? (out + 33554432) : nullptr;

    cudaFuncSetAttribute(qkv_kernel, cudaFuncAttributeMaxDynamicSharedMemorySize, GEMM_SMEM);
    cudaFuncSetAttribute(outproj_kernel, cudaFuncAttributeMaxDynamicSharedMemorySize, GEMM_SMEM);
    cudaFuncSetAttribute(attn_kernel, cudaFuncAttributeMaxDynamicSharedMemorySize, ATT_SMEM);

    // launch order: prep_all, rope, qkv, attn (slot 4 -> profiled), prep_woT, outproj
    prep_all_kernel<<<BV * NTOK + 6144, 128>>>(seq, normw, Wq, Wkv);
    rope_table_kernel<<<2048, 256>>>();

    dim3 g2(12, 512);
    qkv_kernel<<<g2, 256, GEMM_SMEM>>>(vout);

    attn_kernel<<<BV * 256 * HEADS, 256, ATT_SMEM>>>(tm, vout);

    prep_woT_kernel<<<1024, 256>>>(Wo);

    dim3 g4(4, 512);
    outproj_kernel<<<g4, 256, GEMM_SMEM>>>(out);
}

// round 13
// speedup vs baseline: 1.0886x; 1.0886x over previous
#include <cuda_runtime.h>
#include <cuda_fp16.h>
#include <cstdint>
#include <math.h>

#define BV      4
#define NTOK    16384
#define DIMM    512
#define HEADS   8
#define DH      64
#define SEGLEN  64
#define PMT     4

// ---------------- scratch (device globals; no allocation) ----------------
__device__ float  g_rms[BV * NTOK];
__device__ float  g_rope[NTOK * 64];
__device__ __half g_xt[(size_t)BV * NTOK * DIMM];      // fp16 x, K-permuted per 32-block
__device__ __half g_wqkvT[1536 * DIMM];                // fp16(gamma*[Wq|Wkv])^T, K-permuted
__device__ __half g_woT[DIMM * DIMM];                  // fp16(Wo)^T, K-permuted
__device__ float  g_q[(size_t)BV * HEADS * NTOK * DH];
__device__ float  g_k[(size_t)BV * HEADS * NTOK * DH];
__device__ float  g_vfb[(size_t)BV * HEADS * NTOK * DH];
__device__ __half g_att[(size_t)BV * NTOK * DIMM];     // fp16 attention out, K-permuted

// K-permutation within each 32-block (fragment halves contiguous per thread)
__device__ __forceinline__ int kperm(int k) {
    return (((k >> 1) & 3) << 3) + (((k >> 3) & 3) << 1) + (k & 1);
}

// ---------------- cp.async helpers ----------------
__device__ __forceinline__ void cp16a(uint32_t smem, const void* g) {
    asm volatile("cp.async.cg.shared.global [%0], [%1], 16;\n" ::"r"(smem), "l"(g));
}
__device__ __forceinline__ void cp_commit() { asm volatile("cp.async.commit_group;\n"); }
__device__ __forceinline__ void cp_wait1() { asm volatile("cp.async.wait_group 1;\n"); }
__device__ __forceinline__ void cp_wait0() { asm volatile("cp.async.wait_group 0;\n"); }

// fp16 pack/unpack helpers
__device__ __forceinline__ uint2 f4_to_h4(float4 v) {
    __half2 h0 = __floats2half2_rn(v.x, v.y);
    __half2 h1 = __floats2half2_rn(v.z, v.w);
    uint2 r;
    r.x = *(uint32_t*)&h0;
    r.y = *(uint32_t*)&h1;
    return r;
}
__device__ __forceinline__ void h8_to_f8(uint4 u, float* f) {
    __half2* h = (__half2*)&u;
#pragma unroll
    for (int i = 0; i < 4; i++) {
        float2 a = __half22float2(h[i]);
        f[2 * i] = a.x;
        f[2 * i + 1] = a.y;
    }
}

// ---------------- rope table ----------------
__global__ void rope_table_kernel() {
    int idx = blockIdx.x * blockDim.x + threadIdx.x;
    if (idx >= NTOK * 32) return;
    int n = idx >> 5, i = idx & 31;
    double p = pow(10000.0, (double)i / 32.0);
    float inv = 1.0f / (float)p;
    float th = (float)n * inv;
    float s, c;
    sincosf(th, &s, &c);
    g_rope[idx * 2 + 0] = c;
    g_rope[idx * 2 + 1] = s;
}

// ---------------- prep_all: rms (+fp16 permuted x) AND wqkvT prep ----------------
__global__ __launch_bounds__(128) void prep_all_kernel(const float* __restrict__ seq,
                                                       const float* __restrict__ normw,
                                                       const float* __restrict__ Wq,
                                                       const float* __restrict__ Wkv) {
    int bid = blockIdx.x;
    int t = threadIdx.x;
    if (bid < BV * NTOK) {
        int row = bid;
        const float4* p = (const float4*)(seq + (size_t)row * DIMM);
        float4 v = p[t];
        float ss = v.x * v.x + v.y * v.y + v.z * v.z + v.w * v.w;
#pragma unroll
        for (int o = 16; o; o >>= 1) ss += __shfl_xor_sync(0xffffffffu, ss, o);
        __shared__ float wsum[4];
        if ((t & 31) == 0) wsum[t >> 5] = ss;
        __syncthreads();
        if (t == 0) {
            float tot = wsum[0] + wsum[1] + wsum[2] + wsum[3];
            g_rms[row] = rsqrtf(tot * (1.0f / DIMM) + 1.1920929e-7f);
        }
        float vv[4] = {v.x, v.y, v.z, v.w};
        __half* dst = g_xt + (size_t)row * DIMM;
#pragma unroll
        for (int j = 0; j < 4; j++) {
            int k = t * 4 + j;
            dst[(k & ~31) + kperm(k & 31)] = __float2half_rn(vv[j]);
        }
    } else {
        int idx = (bid - BV * NTOK) * 128 + t;
        if (idx < 1536 * DIMM) {
            int n = idx >> 9, kpf = idx & 511;
            int kp = kpf & 31;
            int k = (kpf & ~31) + 8 * ((kp & 7) >> 1) + 2 * (kp >> 3) + (kp & 1);
            float w = (n < 512) ? Wq[k * 512 + n] : Wkv[k * 1024 + (n - 512)];
            g_wqkvT[idx] = __float2half_rn(normw[k] * w);
        }
    }
}

__global__ void prep_woT_kernel(const float* __restrict__ Wo) {
    int idx = blockIdx.x * blockDim.x + threadIdx.x;
    if (idx >= DIMM * DIMM) return;
    int n = idx >> 9, kpf = idx & 511;
    int kp = kpf & 31;
    int k = (kpf & ~31) + 8 * ((kp & 7) >> 1) + 2 * (kp >> 3) + (kp & 1);
    g_woT[idx] = __float2half_rn(Wo[k * 512 + n]);
}

// ================= GEMM core: fp16 m16n8k16 mma, BK=32, 3-stage cp.async ring =================
// (R11 configuration — verified qkv = 439 us)
#define HSTR 32
#define T_STG (128 * HSTR)
#define NSTAGE 3
#define GEMM_SMEM (NSTAGE * 2 * T_STG * 2) // 49152 B

__device__ __forceinline__ void gemm_loadT(uint32_t sbase, const __half* src, int kbase, int t) {
#pragma unroll
    for (int i = 0; i < 2; i++) {
        int c = t + i * 256;
        int row = c >> 2, seg = c & 3;
        cp16a(sbase + (uint32_t)(row * HSTR + seg * 8) * 2,
              src + (size_t)row * DIMM + kbase + seg * 8);
    }
}

__device__ __forceinline__ void gemm_compute(const __half* aB, const __half* bB,
                                             float acc[4][4][4]) {
    uint4 av[4][2], bv[4];
#pragma unroll
    for (int mt = 0; mt < 4; mt++) {
        av[mt][0] = *(const uint4*)(aB + mt * 16 * HSTR);
        av[mt][1] = *(const uint4*)(aB + (mt * 16 + 8) * HSTR);
    }
#pragma unroll
    for (int nt = 0; nt < 4; nt++)
        bv[nt] = *(const uint4*)(bB + nt * 8 * HSTR);
#pragma unroll
    for (int h = 0; h < 2; h++) {
#pragma unroll
        for (int mt = 0; mt < 4; mt++) {
            uint32_t a0 = h ? av[mt][0].z : av[mt][0].x;
            uint32_t a1 = h ? av[mt][1].z : av[mt][1].x;
            uint32_t a2 = h ? av[mt][0].w : av[mt][0].y;
            uint32_t a3 = h ? av[mt][1].w : av[mt][1].y;
#pragma unroll
            for (int nt = 0; nt < 4; nt++) {
                uint32_t b0 = h ? bv[nt].z : bv[nt].x;
                uint32_t b1 = h ? bv[nt].w : bv[nt].y;
                asm volatile(
                    "mma.sync.aligned.m16n8k16.row.col.f32.f16.f16.f32 "
                    "{%0,%1,%2,%3},{%4,%5,%6,%7},{%8,%9},{%0,%1,%2,%3};"
                    : "+f"(acc[mt][nt][0]), "+f"(acc[mt][nt][1]),
                      "+f"(acc[mt][nt][2]), "+f"(acc[mt][nt][3])
                    : "r"(a0), "r"(a1), "r"(a2), "r"(a3),
                      "r"(b0), "r"(b1));
            }
        }
    }
}

__device__ __forceinline__ void gemm_mainloop(__half* sA, __half* sB,
                                              const __half* Ap, const __half* Bp,
                                              float acc[4][4][4],
                                              int aOff, int bOff, int t) {
    uint32_t aS = (uint32_t)__cvta_generic_to_shared(sA);
    uint32_t bS = (uint32_t)__cvta_generic_to_shared(sB);

    gemm_loadT(aS, Ap, 0, t);
    gemm_loadT(bS, Bp, 0, t);
    cp_commit();
    gemm_loadT(aS + T_STG * 2, Ap, 32, t);
    gemm_loadT(bS + T_STG * 2, Bp, 32, t);
    cp_commit();

    int cur = 0, nxt = 2;
#pragma unroll 1
    for (int kt = 0; kt < 16; kt++) {
        if (kt == 15) cp_wait0(); else cp_wait1();
        __syncthreads();
        if (kt + 2 < 16) {
            gemm_loadT(aS + nxt * (T_STG * 2), Ap, (kt + 2) * 32, t);
            gemm_loadT(bS + nxt * (T_STG * 2), Bp, (kt + 2) * 32, t);
            cp_commit();
        }
        gemm_compute(sA + cur * T_STG + aOff, sB + cur * T_STG + bOff, acc);
        cur = (cur == 2) ? 0 : cur + 1;
        nxt = (nxt == 2) ? 0 : nxt + 1;
    }
}

// ---------------- K2: QKV GEMM + RoPE epilogue ----------------
__global__ __launch_bounds__(256, 2) void qkv_kernel(float* __restrict__ vout_opt) {
    extern __shared__ __half smg[];
    __half* sA = smg;
    __half* sB = smg + NSTAGE * T_STG;

    float* vout = vout_opt ? vout_opt : g_vfb;

    int cb = blockIdx.x, rb = blockIdx.y;
    int r0 = rb * 128, c0 = cb * 128;
    int b = r0 >> 14, n0 = r0 & 16383;
    int sec = c0 >> 9;
    int srcb = sec ? (b ^ 2) : b;
    const __half* Ap = g_xt + ((size_t)srcb * NTOK + n0) * DIMM;
    const float* rmsp = g_rms + srcb * NTOK + n0;
    const __half* Bp = g_wqkvT + (size_t)c0 * DIMM;

    int t = threadIdx.x;
    int warp = t >> 5, lane = t & 31;
    int wm = warp >> 2, wn = warp & 3;
    int g = lane >> 2, t4 = lane & 3;
    int aOff = (wm * 64 + g) * HSTR + t4 * 8;
    int bOff = (wn * 32 + g) * HSTR + t4 * 8;

    float acc[4][4][4];
#pragma unroll
    for (int i = 0; i < 4; i++)
#pragma unroll
        for (int j = 0; j < 4; j++)
#pragma unroll
            for (int k = 0; k < 4; k++) acc[i][j][k] = 0.f;

    gemm_mainloop(sA, sB, Ap, Bp, acc, aOff, bOff, t);

#pragma unroll
    for (int mt = 0; mt < 4; mt++)
#pragma unroll
        for (int half = 0; half < 2; half++) {
            int rl = wm * 64 + mt * 16 + g + half * 8;
            float rs = rmsp[rl];
            int n = n0 + rl;
#pragma unroll
            for (int nt = 0; nt < 4; nt++) {
                int c = c0 + wn * 32 + nt * 8 + t4 * 2;
                float e = acc[mt][nt][half * 2 + 0] * rs;
                float o = acc[mt][nt][half * 2 + 1] * rs;
                if (sec < 2) {
                    int cc = c - sec * 512;
                    int h = cc >> 6, d = cc & 63;
                    int fi = d >> 1;
                    float cs = g_rope[((size_t)n * 32 + fi) * 2 + 0];
                    float sn = g_rope[((size_t)n * 32 + fi) * 2 + 1];
                    float re = e * cs - o * sn;
                    float ro = o * cs + e * sn;
                    float* dst = (sec == 0 ? g_q : g_k) +
                                 (((size_t)(b * HEADS + h) * NTOK + n) * DH + d);
                    *(float2*)dst = make_float2(re, ro);
                } else {
                    int cc = c - 1024;
                    int h = cc >> 6, d = cc & 63;
                    *(float2*)(vout + (((size_t)(b * HEADS + h) * NTOK + n) * DH + d)) =
                        make_float2(e, o);
                }
            }
        }
}

// ---------------- K4: output GEMM -> d_out ----------------
__global__ __launch_bounds__(256, 2) void outproj_kernel(float* __restrict__ out) {
    extern __shared__ __half smg[];
    __half* sA = smg;
    __half* sB = smg + NSTAGE * T_STG;

    int cb = blockIdx.x, rb = blockIdx.y;
    int r0 = rb * 128, c0 = cb * 128;
    const __half* Ap = g_att + (size_t)r0 * DIMM;
    const __half* Bp = g_woT + (size_t)c0 * DIMM;

    int t = threadIdx.x;
    int warp = t >> 5, lane = t & 31;
    int wm = warp >> 2, wn = warp & 3;
    int g = lane >> 2, t4 = lane & 3;
    int aOff = (wm * 64 + g) * HSTR + t4 * 8;
    int bOff = (wn * 32 + g) * HSTR + t4 * 8;

    float acc[4][4][4];
#pragma unroll
    for (int i = 0; i < 4; i++)
#pragma unroll
        for (int j = 0; j < 4; j++)
#pragma unroll
            for (int k = 0; k < 4; k++) acc[i][j][k] = 0.f;

    gemm_mainloop(sA, sB, Ap, Bp, acc, aOff, bOff, t);

#pragma unroll
    for (int mt = 0; mt < 4; mt++)
#pragma unroll
        for (int half = 0; half < 2; half++) {
            int r = r0 + wm * 64 + mt * 16 + g + half * 8;
#pragma unroll
            for (int nt = 0; nt < 4; nt++) {
                int c = c0 + wn * 32 + nt * 8 + t4 * 2;
                *(float2*)(out + (size_t)r * DIMM + c) =
                    make_float2(acc[mt][nt][half * 2 + 0], acc[mt][nt][half * 2 + 1]);
            }
        }
}

// ---------------- K3: windowed attention (fp16 operands, f32 math) ----------------
// smem (halves): qh[64][72], kh[80][72] (rows 68..79 zero), vh[68][72]; Ss[64][68] f32
#define QHSTR 72
#define ATT_SMEM ((64 * QHSTR + 80 * QHSTR + 68 * QHSTR) * 2 + 64 * 68 * 4)  // 47936 B

__global__ __launch_bounds__(256, 3) void attn_kernel(const float* __restrict__ tm,
                                                      const float* __restrict__ vsrc_opt) {
    extern __shared__ __half smh[];
    __half* qh = smh;                      // 64 x 72
    __half* kh = qh + 64 * QHSTR;          // 80 x 72
    __half* vh = kh + 80 * QHSTR;          // 68 x 72
    float* Ss = (float*)(vh + 68 * QHSTR); // 64 x 68

    const float* vsrc = vsrc_opt ? vsrc_opt : g_vfb;

    int wh = blockIdx.x;
    int h = wh & 7, win = wh >> 3;
    int b = win >> 8, wi = win & 255;
    int n0 = wi * SEGLEN;
    int t = threadIdx.x;
    size_t base = ((size_t)(b * HEADS + h) * NTOK + n0) * DH;

    const float* tmk = tm + h * (PMT * DH);
    const float* tmv = tm + HEADS * PMT * DH + h * (PMT * DH);

    // fill q: 64 rows x 16 segs of float4 -> fp16
#pragma unroll
    for (int i = 0; i < 4; i++) {
        int c = t + i * 256;
        int row = c >> 4, seg = c & 15;
        float4 v4 = *(const float4*)(g_q + base + (size_t)row * DH + seg * 4);
        *(uint2*)&qh[row * QHSTR + seg * 4] = f4_to_h4(v4);
    }
    // fill k: rows 0..3 task mem, 4..67 g_k, 68..79 zero
#pragma unroll
    for (int i = 0; i < 5; i++) {
        int c = t + i * 256;
        int row = c >> 4, seg = c & 15;
        float4 v4;
        if (row < PMT)
            v4 = *(const float4*)(tmk + row * DH + seg * 4);
        else if (row < 68)
            v4 = *(const float4*)(g_k + base + (size_t)(row - PMT) * DH + seg * 4);
        else
            v4 = make_float4(0.f, 0.f, 0.f, 0.f);
        *(uint2*)&kh[row * QHSTR + seg * 4] = f4_to_h4(v4);
    }
    // fill v: rows 0..3 task mem, 4..67 vsrc (1088 chunks)
#pragma unroll
    for (int i = 0; i < 5; i++) {
        int c = t + i * 256;
        if (c < 68 * 16) {
            int row = c >> 4, seg = c & 15;
            float4 v4;
            if (row < PMT)
                v4 = *(const float4*)(tmv + row * DH + seg * 4);
            else
                v4 = *(const float4*)(vsrc + base + (size_t)(row - PMT) * DH + seg * 4);
            *(uint2*)&vh[row * QHSTR + seg * 4] = f4_to_h4(v4);
        }
    }
    __syncthreads();

    // phase 1: S = Q K^T * 0.125, thread tile 4q x 5j, fp16 loads -> f32 FMA
    int tq = t >> 4, tj = t & 15;
    int qi0 = tq * 4, j0 = tj * 5;
    {
        float accS[4][5];
#pragma unroll
        for (int i = 0; i < 4; i++)
#pragma unroll
            for (int j = 0; j < 5; j++) accS[i][j] = 0.f;
#pragma unroll 2
        for (int d8 = 0; d8 < 64; d8 += 8) {
            float qf[4][8], kf[5][8];
#pragma unroll
            for (int i = 0; i < 4; i++)
                h8_to_f8(*(const uint4*)&qh[(qi0 + i) * QHSTR + d8], qf[i]);
#pragma unroll
            for (int j = 0; j < 5; j++)
                h8_to_f8(*(const uint4*)&kh[(j0 + j) * QHSTR + d8], kf[j]);
#pragma unroll
            for (int i = 0; i < 4; i++)
#pragma unroll
                for (int j = 0; j < 5; j++) {
#pragma unroll
                    for (int dd = 0; dd < 8; dd++)
                        accS[i][j] += qf[i][dd] * kf[j][dd];
                }
        }
#pragma unroll
        for (int i = 0; i < 4; i++)
#pragma unroll
            for (int j = 0; j < 5; j++)
                if (j0 + j < 68) Ss[(qi0 + i) * 68 + j0 + j] = accS[i][j] * 0.125f;
    }
    __syncthreads();

    // softmax: 4 threads per row, 17 elems each, quad shuffle reduction
    {
        int row = t >> 2, q4 = t & 3;
        float* Sr = Ss + row * 68 + q4 * 17;
        float m = -1e30f;
#pragma unroll
        for (int jj = 0; jj < 17; jj++) m = fmaxf(m, Sr[jj]);
        m = fmaxf(m, __shfl_xor_sync(0xffffffffu, m, 1));
        m = fmaxf(m, __shfl_xor_sync(0xffffffffu, m, 2));
        float s = 0.f;
#pragma unroll
        for (int jj = 0; jj < 17; jj++) {
            float e = expf(Sr[jj] - m);
            Sr[jj] = e;
            s += e;
        }
        s += __shfl_xor_sync(0xffffffffu, s, 1);
        s += __shfl_xor_sync(0xffffffffu, s, 2);
        float inv = 1.0f / s;
#pragma unroll
        for (int jj = 0; jj < 17; jj++) Sr[jj] *= inv;
    }
    __syncthreads();

    // phase 2: O = P V, thread tile 4q x 4d, fp16 V from smem
    int td = t & 15, d0 = td * 4;
    float acc[4][4];
#pragma unroll
    for (int i = 0; i < 4; i++)
#pragma unroll
        for (int k = 0; k < 4; k++) acc[i][k] = 0.f;

#pragma unroll 4
    for (int j = 0; j < 68; j++) {
        uint2 u = *(const uint2*)&vh[j * QHSTR + d0];
        __half2* hp = (__half2*)&u;
        float2 va = __half22float2(hp[0]);
        float2 vb = __half22float2(hp[1]);
        float p[4];
#pragma unroll
        for (int i = 0; i < 4; i++) p[i] = Ss[(qi0 + i) * 68 + j];
#pragma unroll
        for (int i = 0; i < 4; i++) {
            acc[i][0] += p[i] * va.x; acc[i][1] += p[i] * va.y;
            acc[i][2] += p[i] * vb.x; acc[i][3] += p[i] * vb.y;
        }
    }

    // fp16 K-permuted store into g_att
#pragma unroll
    for (int i = 0; i < 4; i++) {
        __half* op = g_att + ((size_t)(b * NTOK + n0 + qi0 + i)) * DIMM + h * DH;
#pragma unroll
        for (int j = 0; j < 4; j++) {
            int d = d0 + j;
            op[(d & ~31) + kperm(d & 31)] = __float2half_rn(acc[i][j]);
        }
    }
}

// ---------------- launch ----------------
extern "C" void kernel_launch(void* const* d_in, const int* in_sizes, int n_in,
                              void* d_out, int out_size) {
    const float *seq = 0, *normw = 0, *Wq = 0, *Wkv = 0, *Wo = 0, *tm = 0;
    for (int i = 0; i < n_in; i++) {
        int s = in_sizes[i];
        const float* p = (const float*)d_in[i];
        if (s == 33554432) seq = p;
        else if (s == 512) normw = p;
        else if (s == 524288) Wkv = p;
        else if (s == 4096) tm = p;
        else if (s == 262144) { if (!Wq) Wq = p; else Wo = p; }
    }
    float* out = (float*)d_out;
    float* vout = (out_size >= 67108864) ? (out + 33554432) : nullptr;

    cudaFuncSetAttribute(qkv_kernel, cudaFuncAttributeMaxDynamicSharedMemorySize, GEMM_SMEM);
    cudaFuncSetAttribute(outproj_kernel, cudaFuncAttributeMaxDynamicSharedMemorySize, GEMM_SMEM);
    cudaFuncSetAttribute(attn_kernel, cudaFuncAttributeMaxDynamicSharedMemorySize, ATT_SMEM);

    // launch order: prep_all, rope, qkv, attn (slot 4 -> profiled), prep_woT, outproj
    prep_all_kernel<<<BV * NTOK + 6144, 128>>>(seq, normw, Wq, Wkv);
    rope_table_kernel<<<2048, 256>>>();

    dim3 g2(12, 512);
    qkv_kernel<<<g2, 256, GEMM_SMEM>>>(vout);

    attn_kernel<<<BV * 256 * HEADS, 256, ATT_SMEM>>>(tm, vout);

    prep_woT_kernel<<<1024, 256>>>(Wo);

    dim3 g4(4, 512);
    outproj_kernel<<<g4, 256, GEMM_SMEM>>>(out);
}